// round 13
// baseline (speedup 1.0000x reference)
#include <cuda_runtime.h>
#include <math_constants.h>

#define NN    10000
#define EE    160000
#define SNAP  16       // B*T
#define TT    8
#define BB    2
#define CIN   64
#define CC    32
#define SLOTS 96       // padded bucket capacity per node (max degree ~40)
#define XCH   256      // rows per xlr block
#define XPAD  66       // smem row stride (floats): 2-way max bank conflicts

// ---------------- static device scratch (zero-initialized at load) ----------------
__device__ float g_xl[NN * SNAP * CC];       // [n][s][c]
__device__ float g_xr[NN * SNAP * CC];       // [n][s][c]
__device__ float g_loop_sum[NN * 3];
__device__ int   g_cursor[NN];               // per-node in-degree / bucket cursor
__device__ int4  g_bkt[NN * SLOTS];          // {src, attr0, attr1, attr2}

__global__ void k_nop() {}                   // ncu launch-index alignment

// ---------------- build: bucket scatter + loop_sum in ONE kernel ----------------
__global__ void k_build(const int* __restrict__ ei, const float* __restrict__ ea) {
    int e = blockIdx.x * blockDim.x + threadIdx.x;
    if (e >= EE) return;
    int src = ei[e];
    int dst = ei[EE + e];
    float a0 = ea[e * 3 + 0], a1 = ea[e * 3 + 1], a2 = ea[e * 3 + 2];
    atomicAdd(&g_loop_sum[dst * 3 + 0], a0);
    atomicAdd(&g_loop_sum[dst * 3 + 1], a1);
    atomicAdd(&g_loop_sum[dst * 3 + 2], a2);
    int pos = atomicAdd(&g_cursor[dst], 1);
    g_bkt[dst * SLOTS + pos] =
        make_int4(src, __float_as_int(a0), __float_as_int(a1), __float_as_int(a2));
}

// ---------------- xlr v3: lane = row, zero shuffles ----------------
__global__ void __launch_bounds__(256) k_xlr(const float* __restrict__ x,
                      const float* __restrict__ W_l, const float* __restrict__ b_l,
                      const float* __restrict__ W_r, const float* __restrict__ b_r) {
    extern __shared__ float sx[];            // [XCH][XPAD]
    __shared__ float4 sW[CIN][16];
    __shared__ float2 sB[CC];

    int tid = threadIdx.x;
    for (int i = tid; i < CIN * 16; i += 256) {
        int k = i >> 4, cp = i & 15;
        sW[k][cp] = make_float4(W_l[k * 32 + 2 * cp],     W_r[k * 32 + 2 * cp],
                                W_l[k * 32 + 2 * cp + 1], W_r[k * 32 + 2 * cp + 1]);
    }
    if (tid < CC) sB[tid] = make_float2(b_l[tid], b_r[tid]);

    int rbase = blockIdx.x * XCH;            // grid 625 exact
    {
        const float2* xg = (const float2*)(x + (long)rbase * CIN);
        for (int i = tid; i < XCH * 32; i += 256) {
            int row = i >> 5, q = i & 31;
            *(float2*)&sx[row * XPAD + q * 2] = xg[row * 32 + q];
        }
    }
    __syncthreads();

    int w = tid >> 5, lane = tid & 31;
    int rloc = w * 32 + lane;
    int rglob = rbase + rloc;

    float accl[32], accr[32];
#pragma unroll
    for (int c = 0; c < 32; c++) {
        float2 b = sB[c];
        accl[c] = b.x;
        accr[c] = b.y;
    }

    const float* xrow = &sx[rloc * XPAD];
#pragma unroll 4
    for (int k = 0; k < CIN; k++) {
        float xk = xrow[k];
#pragma unroll
        for (int cp = 0; cp < 16; cp++) {
            float4 wv = sW[k][cp];
            accl[2 * cp]     += xk * wv.x;
            accr[2 * cp]     += xk * wv.y;
            accl[2 * cp + 1] += xk * wv.z;
            accr[2 * cp + 1] += xk * wv.w;
        }
    }

    int s = rglob / NN, n = rglob - s * NN;
    float4* outl = (float4*)(g_xl + (n * SNAP + s) * 32);
    float4* outr = (float4*)(g_xr + (n * SNAP + s) * 32);
#pragma unroll
    for (int c4 = 0; c4 < 8; c4++) {
        outl[c4] = make_float4(accl[4 * c4], accl[4 * c4 + 1],
                               accl[4 * c4 + 2], accl[4 * c4 + 3]);
        outr[c4] = make_float4(accr[4 * c4], accr[4 * c4 + 1],
                               accr[4 * c4 + 2], accr[4 * c4 + 3]);
    }
}

// Fused GATv2 + GRU: warp per node; slim GAT register set -> 3 blocks/SM.
__global__ void __launch_bounds__(256, 3) k_gatgru(
        const float* __restrict__ W_e,
        const float* __restrict__ att, const float* __restrict__ bias_gat,
        const float* __restrict__ W_ih, const float* __restrict__ W_hh,
        const float* __restrict__ b_ih, const float* __restrict__ b_hh,
        float* __restrict__ out) {
    __shared__ float4 sWA[32][32];     // [h][c] = {wi_r, wh_r, wi_z, wh_z}
    __shared__ float2 sWB[32][32];     // [h][c] = {wi_n, wh_n}
    __shared__ float  sb[6][32];
    __shared__ float4 swe[3][8];       // W_e rows, indexed by q
    __shared__ float4 sat[8];          // att, indexed by q
    __shared__ float2 s_tr[8][8][32];  // [warp][t][c] = {batch0, batch1}

    int tid = threadIdx.x;
    for (int i = tid; i < 1024; i += 256) {
        int c = i & 31, hh = i >> 5;
        sWA[hh][c] = make_float4(W_ih[c * 32 + hh],        W_hh[c * 32 + hh],
                                 W_ih[(32 + c) * 32 + hh], W_hh[(32 + c) * 32 + hh]);
        sWB[hh][c] = make_float2(W_ih[(64 + c) * 32 + hh], W_hh[(64 + c) * 32 + hh]);
    }
    if (tid < 96) {
        int g = tid >> 5, c = tid & 31;
        sb[g][c] = b_ih[tid];
        sb[3 + g][c] = b_hh[tid];
    }
    if (tid < 24) swe[tid >> 3][tid & 7] = ((const float4*)W_e)[(tid >> 3) * 8 + (tid & 7)];
    if (tid < 8) sat[tid] = ((const float4*)att)[tid];
    __syncthreads();

    int w = tid >> 5, lane = tid & 31;
    int n = blockIdx.x * 8 + w;            // grid = NN/8 exact
    int q = lane & 7;

    int deg = g_cursor[n];

    float4 xr4[4];
    {
        const float4* p = (const float4*)(g_xr + n * SNAP * 32);
#pragma unroll
        for (int k = 0; k < 4; k++) xr4[k] = p[k * 32 + lane];
    }

    float4 acc[4];
#pragma unroll
    for (int k = 0; k < 4; k++) acc[k] = make_float4(0.f, 0.f, 0.f, 0.f);
    float ssum[4] = {0.f, 0.f, 0.f, 0.f};

    const int4* bkt = g_bkt + n * SLOTS;

#define GAT_EDGE(A, EB, VALID)                                              \
    do {                                                                    \
        float a0 = __int_as_float(EB.y);                                    \
        float a1 = __int_as_float(EB.z);                                    \
        float a2 = __int_as_float(EB.w);                                    \
        float4 w0 = swe[0][q], w1 = swe[1][q], w2 = swe[2][q];              \
        float4 at4 = sat[q];                                                \
        float4 ev;                                                          \
        ev.x = a0 * w0.x + a1 * w1.x + a2 * w2.x;                           \
        ev.y = a0 * w0.y + a1 * w1.y + a2 * w2.y;                           \
        ev.z = a0 * w0.z + a1 * w1.z + a2 * w2.z;                           \
        ev.w = a0 * w0.w + a1 * w1.w + a2 * w2.w;                           \
        float d[4];                                                         \
        _Pragma("unroll")                                                   \
        for (int k = 0; k < 4; k++) {                                       \
            float v0 = A[k].x + ev.x + xr4[k].x;                            \
            float v1 = A[k].y + ev.y + xr4[k].y;                            \
            float v2 = A[k].z + ev.z + xr4[k].z;                            \
            float v3 = A[k].w + ev.w + xr4[k].w;                            \
            v0 = fmaxf(v0, 0.2f * v0);                                      \
            v1 = fmaxf(v1, 0.2f * v1);                                      \
            v2 = fmaxf(v2, 0.2f * v2);                                      \
            v3 = fmaxf(v3, 0.2f * v3);                                      \
            d[k] = v0 * at4.x + v1 * at4.y + v2 * at4.z + v3 * at4.w;       \
        }                                                                   \
        _Pragma("unroll")                                                   \
        for (int o = 1; o < 8; o <<= 1) {                                   \
            _Pragma("unroll")                                               \
            for (int k = 0; k < 4; k++)                                     \
                d[k] += __shfl_xor_sync(0xffffffffu, d[k], o);              \
        }                                                                   \
        _Pragma("unroll")                                                   \
        for (int k = 0; k < 4; k++) {                                       \
            float wv = (VALID) ? __expf(d[k]) : 0.f;                        \
            ssum[k] += wv;                                                  \
            acc[k].x += wv * A[k].x;                                        \
            acc[k].y += wv * A[k].y;                                        \
            acc[k].z += wv * A[k].z;                                        \
            acc[k].w += wv * A[k].w;                                        \
        }                                                                   \
    } while (0)

    // main loop over REAL edges only (ping-pong, depth-1 prefetch)
    if (deg > 0) {
        int4 eb0 = bkt[0];
        float4 a[4];
        {
            const float4* xp = (const float4*)(g_xl + eb0.x * SNAP * 32);
#pragma unroll
            for (int k = 0; k < 4; k++) a[k] = xp[k * 32 + lane];
        }
        for (int j = 0; j < deg; j += 2) {
            int j1 = (j + 1 < deg) ? j + 1 : j;
            int4 eb1 = bkt[j1];
            const float4* xp1 = (const float4*)(g_xl + eb1.x * SNAP * 32);
            float4 an[4];
#pragma unroll
            for (int k = 0; k < 4; k++) an[k] = xp1[k * 32 + lane];

            GAT_EDGE(a, eb0, true);

            int j2 = (j + 2 < deg) ? j + 2 : deg - 1;
            eb0 = bkt[j2];
            const float4* xp2 = (const float4*)(g_xl + eb0.x * SNAP * 32);
#pragma unroll
            for (int k = 0; k < 4; k++) a[k] = xp2[k * 32 + lane];

            GAT_EDGE(an, eb1, (j + 1 < deg));
        }
    }

    // self-loop tail (attrs = segment mean; src = n)
    {
        float invc = 1.f / fmaxf((float)deg, 1.f);
        int4 ebs = make_int4(n,
            __float_as_int(g_loop_sum[n * 3 + 0] * invc),
            __float_as_int(g_loop_sum[n * 3 + 1] * invc),
            __float_as_int(g_loop_sum[n * 3 + 2] * invc));
        const float4* xps = (const float4*)(g_xl + n * SNAP * 32);
        float4 as[4];
#pragma unroll
        for (int k = 0; k < 4; k++) as[k] = xps[k * 32 + lane];
        GAT_EDGE(as, ebs, true);
    }
#undef GAT_EDGE

    {
        const float4 bi4 = *(const float4*)(bias_gat + 4 * q);
        int g = lane >> 3;
#pragma unroll
        for (int k = 0; k < 4; k++) {
            float inv = 1.f / ssum[k];
            int s = 4 * k + g;
            int b = s >> 3, t = s & 7;
            float* tp = (float*)&s_tr[w][t][4 * q];
            tp[0 * 2 + b] = acc[k].x * inv + bi4.x;
            tp[1 * 2 + b] = acc[k].y * inv + bi4.y;
            tp[2 * 2 + b] = acc[k].z * inv + bi4.z;
            tp[3 * 2 + b] = acc[k].w * inv + bi4.w;
        }
    }
    __syncwarp();

    // ---- GRU phase: lane = channel c; 2 sequences (b=0, b=1)
    int c = lane;
    float bi0 = sb[0][c], bi1 = sb[1][c], bi2 = sb[2][c];
    float bh0 = sb[3][c], bh1 = sb[4][c], bh2 = sb[5][c];

    float h0 = 0.f, h1 = 0.f;
    for (int t = 0; t < TT; t++) {
        float ir0 = bi0, iz0 = bi1, in0 = bi2, hr0 = bh0, hz0 = bh1, hn0 = bh2;
        float ir1 = bi0, iz1 = bi1, in1 = bi2, hr1 = bh0, hz1 = bh1, hn1 = bh2;
#pragma unroll
        for (int hh = 0; hh < 32; hh++) {
            float2 xv = s_tr[w][t][hh];
            float hv0 = __shfl_sync(0xffffffffu, h0, hh);
            float hv1 = __shfl_sync(0xffffffffu, h1, hh);
            float4 wA = sWA[hh][c];
            float2 wB = sWB[hh][c];
            ir0 += xv.x * wA.x; hr0 += hv0 * wA.y;
            iz0 += xv.x * wA.z; hz0 += hv0 * wA.w;
            in0 += xv.x * wB.x; hn0 += hv0 * wB.y;
            ir1 += xv.y * wA.x; hr1 += hv1 * wA.y;
            iz1 += xv.y * wA.z; hz1 += hv1 * wA.w;
            in1 += xv.y * wB.x; hn1 += hv1 * wB.y;
        }
        {
            float r = 1.f / (1.f + __expf(-(ir0 + hr0)));
            float z = 1.f / (1.f + __expf(-(iz0 + hz0)));
            float pre = in0 + r * hn0;
            float e2 = __expf(-2.f * pre);
            float nn_ = 2.f / (1.f + e2) - 1.f;
            h0 = (1.f - z) * nn_ + z * h0;
            out[((long)t * NN + n) * 32 + c] = h0;
        }
        {
            float r = 1.f / (1.f + __expf(-(ir1 + hr1)));
            float z = 1.f / (1.f + __expf(-(iz1 + hz1)));
            float pre = in1 + r * hn1;
            float e2 = __expf(-2.f * pre);
            float nn_ = 2.f / (1.f + e2) - 1.f;
            h1 = (1.f - z) * nn_ + z * h1;
            out[((long)(TT + t) * NN + n) * 32 + c] = h1;
        }
    }

    // epilogue: re-zero per-node counters for the NEXT replay (this warp owns n)
    if (lane < 3) g_loop_sum[n * 3 + lane] = 0.f;
    else if (lane == 3) g_cursor[n] = 0;
}

// ---------------- launch: dummy + 3 kernels, xlr forked ----------------
extern "C" void kernel_launch(void* const* d_in, const int* in_sizes, int n_in,
                              void* d_out, int out_size) {
    const float* x        = (const float*)d_in[0];
    const int*   ei       = (const int*)d_in[1];
    const float* eattr    = (const float*)d_in[2];
    const float* W_l      = (const float*)d_in[3];
    const float* b_l      = (const float*)d_in[4];
    const float* W_r      = (const float*)d_in[5];
    const float* b_r      = (const float*)d_in[6];
    const float* W_e      = (const float*)d_in[7];
    const float* att      = (const float*)d_in[8];
    const float* bias_gat = (const float*)d_in[9];
    const float* W_ih     = (const float*)d_in[10];
    const float* W_hh     = (const float*)d_in[11];
    const float* b_ih     = (const float*)d_in[12];
    const float* b_hh     = (const float*)d_in[13];
    float* out = (float*)d_out;

    static cudaStream_t s1 = nullptr;
    static cudaEvent_t eRoot = nullptr, eXlr = nullptr;
    if (s1 == nullptr) {
        cudaStreamCreateWithFlags(&s1, cudaStreamNonBlocking);
        cudaEventCreateWithFlags(&eRoot, cudaEventDisableTiming);
        cudaEventCreateWithFlags(&eXlr, cudaEventDisableTiming);
        cudaFuncSetAttribute(k_xlr, cudaFuncAttributeMaxDynamicSharedMemorySize,
                             XCH * XPAD * (int)sizeof(float));
    }

    k_nop<<<1, 32>>>();   // keeps ncu -s5 window on k_gatgru

    cudaEventRecord(eRoot, 0);
    cudaStreamWaitEvent(s1, eRoot, 0);
    k_xlr<<<SNAP * NN / XCH, 256, XCH * XPAD * sizeof(float), s1>>>(x, W_l, b_l, W_r, b_r);
    cudaEventRecord(eXlr, s1);

    k_build<<<(EE + 255) / 256, 256>>>(ei, eattr);

    cudaStreamWaitEvent(0, eXlr, 0);
    k_gatgru<<<NN / 8, 256>>>(W_e, att, bias_gat, W_ih, W_hh, b_ih, b_hh, out);
}

// round 15
// speedup vs baseline: 1.3063x; 1.3063x over previous
#include <cuda_runtime.h>
#include <math_constants.h>

#define NN    10000
#define EE    160000
#define SNAP  16       // B*T
#define TT    8
#define BB    2
#define CIN   64
#define CC    32
#define SLOTS 96       // padded bucket capacity per node (max degree ~40)
#define XCH   256      // rows per xlr block
#define XPAD  66       // smem row stride (floats): 2-way max bank conflicts

// ---------------- static device scratch (zero-initialized at load) ----------------
__device__ float g_xl[NN * SNAP * CC];       // [n][s][c]
__device__ float g_xr[NN * SNAP * CC];       // [n][s][c]
__device__ float g_loop_sum[NN * 3];
__device__ int   g_cursor[NN];               // per-node in-degree / bucket cursor
__device__ int4  g_bkt[NN * SLOTS];          // {src, attr0, attr1, attr2}

__global__ void k_nop() {}                   // ncu launch-index alignment

// ---------------- build: bucket scatter + loop_sum in ONE kernel ----------------
__global__ void k_build(const int* __restrict__ ei, const float* __restrict__ ea) {
    int e = blockIdx.x * blockDim.x + threadIdx.x;
    if (e >= EE) return;
    int src = ei[e];
    int dst = ei[EE + e];
    float a0 = ea[e * 3 + 0], a1 = ea[e * 3 + 1], a2 = ea[e * 3 + 2];
    atomicAdd(&g_loop_sum[dst * 3 + 0], a0);
    atomicAdd(&g_loop_sum[dst * 3 + 1], a1);
    atomicAdd(&g_loop_sum[dst * 3 + 2], a2);
    int pos = atomicAdd(&g_cursor[dst], 1);
    g_bkt[dst * SLOTS + pos] =
        make_int4(src, __float_as_int(a0), __float_as_int(a1), __float_as_int(a2));
}

// ---------------- xlr v3: lane = row, zero shuffles ----------------
__global__ void __launch_bounds__(256) k_xlr(const float* __restrict__ x,
                      const float* __restrict__ W_l, const float* __restrict__ b_l,
                      const float* __restrict__ W_r, const float* __restrict__ b_r) {
    extern __shared__ float sx[];            // [XCH][XPAD]
    __shared__ float4 sW[CIN][16];
    __shared__ float2 sB[CC];

    int tid = threadIdx.x;
    for (int i = tid; i < CIN * 16; i += 256) {
        int k = i >> 4, cp = i & 15;
        sW[k][cp] = make_float4(W_l[k * 32 + 2 * cp],     W_r[k * 32 + 2 * cp],
                                W_l[k * 32 + 2 * cp + 1], W_r[k * 32 + 2 * cp + 1]);
    }
    if (tid < CC) sB[tid] = make_float2(b_l[tid], b_r[tid]);

    int rbase = blockIdx.x * XCH;            // grid 625 exact
    {
        const float2* xg = (const float2*)(x + (long)rbase * CIN);
        for (int i = tid; i < XCH * 32; i += 256) {
            int row = i >> 5, q = i & 31;
            *(float2*)&sx[row * XPAD + q * 2] = xg[row * 32 + q];
        }
    }
    __syncthreads();

    int w = tid >> 5, lane = tid & 31;
    int rloc = w * 32 + lane;
    int rglob = rbase + rloc;

    float accl[32], accr[32];
#pragma unroll
    for (int c = 0; c < 32; c++) {
        float2 b = sB[c];
        accl[c] = b.x;
        accr[c] = b.y;
    }

    const float* xrow = &sx[rloc * XPAD];
#pragma unroll 4
    for (int k = 0; k < CIN; k++) {
        float xk = xrow[k];
#pragma unroll
        for (int cp = 0; cp < 16; cp++) {
            float4 wv = sW[k][cp];
            accl[2 * cp]     += xk * wv.x;
            accr[2 * cp]     += xk * wv.y;
            accl[2 * cp + 1] += xk * wv.z;
            accr[2 * cp + 1] += xk * wv.w;
        }
    }

    int s = rglob / NN, n = rglob - s * NN;
    float4* outl = (float4*)(g_xl + (n * SNAP + s) * 32);
    float4* outr = (float4*)(g_xr + (n * SNAP + s) * 32);
#pragma unroll
    for (int c4 = 0; c4 < 8; c4++) {
        outl[c4] = make_float4(accl[4 * c4], accl[4 * c4 + 1],
                               accl[4 * c4 + 2], accl[4 * c4 + 3]);
        outr[c4] = make_float4(accr[4 * c4], accr[4 * c4 + 1],
                               accr[4 * c4 + 2], accr[4 * c4 + 3]);
    }
}

// Dynamic-smem layout for k_gatgru (~60KB < 48KB static cap, hence dynamic)
struct GGSmem {
    float4 sWA[32][32];     // [h][c] = {wi_r, wh_r, wi_z, wh_z}   16KB
    float2 sWB[32][32];     // [h][c] = {wi_n, wh_n}                8KB
    float2 s_tr[16][8][32]; // [nodeLocal][t][c] = {b0, b1}        32KB
    float2 s_h[8][2][32];   // [warp][nodeSel][c]                   2KB
    float  sb[6][32];
    float4 swe[3][8];
    float4 sat[8];
};

// Fused GATv2 + GRU. Block = 16 nodes, 8 warps.
// GAT: each warp processes 2 nodes sequentially.
// GRU: each warp runs 4 sequences (2 nodes x 2 batches) sharing one
// weight-read stream -> GRU smem wavefronts per sequence nearly halve.
__global__ void __launch_bounds__(256, 2) k_gatgru(
        const float* __restrict__ W_e,
        const float* __restrict__ att, const float* __restrict__ bias_gat,
        const float* __restrict__ W_ih, const float* __restrict__ W_hh,
        const float* __restrict__ b_ih, const float* __restrict__ b_hh,
        float* __restrict__ out) {
    extern __shared__ char ggsm_raw[];
    GGSmem& S = *reinterpret_cast<GGSmem*>(ggsm_raw);

    int tid = threadIdx.x;
    for (int i = tid; i < 1024; i += 256) {
        int c = i & 31, hh = i >> 5;
        S.sWA[hh][c] = make_float4(W_ih[c * 32 + hh],        W_hh[c * 32 + hh],
                                   W_ih[(32 + c) * 32 + hh], W_hh[(32 + c) * 32 + hh]);
        S.sWB[hh][c] = make_float2(W_ih[(64 + c) * 32 + hh], W_hh[(64 + c) * 32 + hh]);
    }
    if (tid < 96) {
        int g = tid >> 5, c = tid & 31;
        S.sb[g][c] = b_ih[tid];
        S.sb[3 + g][c] = b_hh[tid];
    }
    if (tid < 24) S.swe[tid >> 3][tid & 7] = ((const float4*)W_e)[(tid >> 3) * 8 + (tid & 7)];
    if (tid < 8) S.sat[tid] = ((const float4*)att)[tid];
    __syncthreads();

    int w = tid >> 5, lane = tid & 31;
    int nbase = blockIdx.x * 16 + w * 2;   // grid = NN/16 exact
    int q = lane & 7, g = lane >> 3;

#define GAT_EDGE(A, EB, VALID)                                              \
    do {                                                                    \
        float a0 = __int_as_float(EB.y);                                    \
        float a1 = __int_as_float(EB.z);                                    \
        float a2 = __int_as_float(EB.w);                                    \
        float4 w0 = S.swe[0][q], w1 = S.swe[1][q], w2 = S.swe[2][q];        \
        float4 at4 = S.sat[q];                                              \
        float4 ev;                                                          \
        ev.x = a0 * w0.x + a1 * w1.x + a2 * w2.x;                           \
        ev.y = a0 * w0.y + a1 * w1.y + a2 * w2.y;                           \
        ev.z = a0 * w0.z + a1 * w1.z + a2 * w2.z;                           \
        ev.w = a0 * w0.w + a1 * w1.w + a2 * w2.w;                           \
        float d[4];                                                         \
        _Pragma("unroll")                                                   \
        for (int k = 0; k < 4; k++) {                                       \
            float v0 = A[k].x + ev.x + xr4[k].x;                            \
            float v1 = A[k].y + ev.y + xr4[k].y;                            \
            float v2 = A[k].z + ev.z + xr4[k].z;                            \
            float v3 = A[k].w + ev.w + xr4[k].w;                            \
            v0 = fmaxf(v0, 0.2f * v0);                                      \
            v1 = fmaxf(v1, 0.2f * v1);                                      \
            v2 = fmaxf(v2, 0.2f * v2);                                      \
            v3 = fmaxf(v3, 0.2f * v3);                                      \
            d[k] = v0 * at4.x + v1 * at4.y + v2 * at4.z + v3 * at4.w;       \
        }                                                                   \
        _Pragma("unroll")                                                   \
        for (int o = 1; o < 8; o <<= 1) {                                   \
            _Pragma("unroll")                                               \
            for (int k = 0; k < 4; k++)                                     \
                d[k] += __shfl_xor_sync(0xffffffffu, d[k], o);              \
        }                                                                   \
        _Pragma("unroll")                                                   \
        for (int k = 0; k < 4; k++) {                                       \
            float wv = (VALID) ? __expf(d[k]) : 0.f;                        \
            ssum[k] += wv;                                                  \
            acc[k].x += wv * A[k].x;                                        \
            acc[k].y += wv * A[k].y;                                        \
            acc[k].z += wv * A[k].z;                                        \
            acc[k].w += wv * A[k].w;                                        \
        }                                                                   \
    } while (0)

    for (int i = 0; i < 2; i++) {
        int n = nbase + i;
        int deg = g_cursor[n];

        float4 xr4[4];
        {
            const float4* p = (const float4*)(g_xr + n * SNAP * 32);
#pragma unroll
            for (int k = 0; k < 4; k++) xr4[k] = p[k * 32 + lane];
        }
        float4 acc[4];
#pragma unroll
        for (int k = 0; k < 4; k++) acc[k] = make_float4(0.f, 0.f, 0.f, 0.f);
        float ssum[4] = {0.f, 0.f, 0.f, 0.f};

        const int4* bkt = g_bkt + n * SLOTS;

        if (deg > 0) {
            int4 eb0 = bkt[0];
            float4 a[4];
            {
                const float4* xp = (const float4*)(g_xl + eb0.x * SNAP * 32);
#pragma unroll
                for (int k = 0; k < 4; k++) a[k] = xp[k * 32 + lane];
            }
            for (int j = 0; j < deg; j += 2) {
                int j1 = (j + 1 < deg) ? j + 1 : j;
                int4 eb1 = bkt[j1];
                const float4* xp1 = (const float4*)(g_xl + eb1.x * SNAP * 32);
                float4 an[4];
#pragma unroll
                for (int k = 0; k < 4; k++) an[k] = xp1[k * 32 + lane];

                GAT_EDGE(a, eb0, true);

                int j2 = (j + 2 < deg) ? j + 2 : deg - 1;
                eb0 = bkt[j2];
                const float4* xp2 = (const float4*)(g_xl + eb0.x * SNAP * 32);
#pragma unroll
                for (int k = 0; k < 4; k++) a[k] = xp2[k * 32 + lane];

                GAT_EDGE(an, eb1, (j + 1 < deg));
            }
        }

        // self-loop tail (attrs = segment mean; src = n)
        {
            float invc = 1.f / fmaxf((float)deg, 1.f);
            int4 ebs = make_int4(n,
                __float_as_int(g_loop_sum[n * 3 + 0] * invc),
                __float_as_int(g_loop_sum[n * 3 + 1] * invc),
                __float_as_int(g_loop_sum[n * 3 + 2] * invc));
            const float4* xps = (const float4*)(g_xl + n * SNAP * 32);
            float4 as[4];
#pragma unroll
            for (int k = 0; k < 4; k++) as[k] = xps[k * 32 + lane];
            GAT_EDGE(as, ebs, true);
        }

        // write normalized + biased result into transpose buffer
        {
            const float4 bi4 = *(const float4*)(bias_gat + 4 * q);
            int nl = w * 2 + i;
#pragma unroll
            for (int k = 0; k < 4; k++) {
                float inv = 1.f / ssum[k];
                int s = 4 * k + g;
                int b = s >> 3, t = s & 7;
                float* tp = (float*)&S.s_tr[nl][t][4 * q];
                tp[0 * 2 + b] = acc[k].x * inv + bi4.x;
                tp[1 * 2 + b] = acc[k].y * inv + bi4.y;
                tp[2 * 2 + b] = acc[k].z * inv + bi4.z;
                tp[3 * 2 + b] = acc[k].w * inv + bi4.w;
            }
        }
    }
#undef GAT_EDGE
    __syncwarp();

    // ---- GRU phase: lane = channel c; 4 sequences (2 nodes x 2 batches)
    int c = lane;
    int nl0 = w * 2, nl1 = w * 2 + 1;
    int n0 = nbase, n1 = nbase + 1;
    float bi0 = S.sb[0][c], bi1 = S.sb[1][c], bi2 = S.sb[2][c];
    float bh0 = S.sb[3][c], bh1 = S.sb[4][c], bh2 = S.sb[5][c];

    float h00 = 0.f, h01 = 0.f, h10 = 0.f, h11 = 0.f;  // [node][batch]
    for (int t = 0; t < TT; t++) {
        S.s_h[w][0][c] = make_float2(h00, h01);
        S.s_h[w][1][c] = make_float2(h10, h11);
        __syncwarp();

        float ir00 = bi0, iz00 = bi1, in00 = bi2, hr00 = bh0, hz00 = bh1, hn00 = bh2;
        float ir01 = bi0, iz01 = bi1, in01 = bi2, hr01 = bh0, hz01 = bh1, hn01 = bh2;
        float ir10 = bi0, iz10 = bi1, in10 = bi2, hr10 = bh0, hz10 = bh1, hn10 = bh2;
        float ir11 = bi0, iz11 = bi1, in11 = bi2, hr11 = bh0, hz11 = bh1, hn11 = bh2;
#pragma unroll
        for (int hh = 0; hh < 32; hh++) {
            float2 xv0 = S.s_tr[nl0][t][hh];   // broadcast {b0,b1} node0
            float2 xv1 = S.s_tr[nl1][t][hh];   // broadcast node1
            float2 hv0 = S.s_h[w][0][hh];      // broadcast h node0
            float2 hv1 = S.s_h[w][1][hh];      // broadcast h node1
            float4 wA = S.sWA[hh][c];
            float2 wB = S.sWB[hh][c];
            ir00 += xv0.x * wA.x; hr00 += hv0.x * wA.y;
            iz00 += xv0.x * wA.z; hz00 += hv0.x * wA.w;
            in00 += xv0.x * wB.x; hn00 += hv0.x * wB.y;
            ir01 += xv0.y * wA.x; hr01 += hv0.y * wA.y;
            iz01 += xv0.y * wA.z; hz01 += hv0.y * wA.w;
            in01 += xv0.y * wB.x; hn01 += hv0.y * wB.y;
            ir10 += xv1.x * wA.x; hr10 += hv1.x * wA.y;
            iz10 += xv1.x * wA.z; hz10 += hv1.x * wA.w;
            in10 += xv1.x * wB.x; hn10 += hv1.x * wB.y;
            ir11 += xv1.y * wA.x; hr11 += hv1.y * wA.y;
            iz11 += xv1.y * wA.z; hz11 += hv1.y * wA.w;
            in11 += xv1.y * wB.x; hn11 += hv1.y * wB.y;
        }
#define GRU_OUT(IR, HR, IZ, HZ, IN, HN, H, B, N)                            \
        do {                                                                \
            float r = 1.f / (1.f + __expf(-((IR) + (HR))));                 \
            float z = 1.f / (1.f + __expf(-((IZ) + (HZ))));                 \
            float pre = (IN) + r * (HN);                                    \
            float e2 = __expf(-2.f * pre);                                  \
            float nn_ = 2.f / (1.f + e2) - 1.f;                             \
            H = (1.f - z) * nn_ + z * H;                                    \
            out[((long)((B) * TT + t) * NN + (N)) * 32 + c] = H;            \
        } while (0)
        GRU_OUT(ir00, hr00, iz00, hz00, in00, hn00, h00, 0, n0);
        GRU_OUT(ir01, hr01, iz01, hz01, in01, hn01, h01, 1, n0);
        GRU_OUT(ir10, hr10, iz10, hz10, in10, hn10, h10, 0, n1);
        GRU_OUT(ir11, hr11, iz11, hz11, in11, hn11, h11, 1, n1);
#undef GRU_OUT
        __syncwarp();   // protect s_h WAR before next iteration's store
    }

    // epilogue: re-zero per-node counters for the NEXT replay (warp owns n0,n1)
    if (lane < 3) g_loop_sum[n0 * 3 + lane] = 0.f;
    else if (lane == 3) g_cursor[n0] = 0;
    else if (lane >= 4 && lane < 7) g_loop_sum[n1 * 3 + (lane - 4)] = 0.f;
    else if (lane == 7) g_cursor[n1] = 0;
}

// ---------------- launch: dummy + 3 kernels, xlr forked ----------------
extern "C" void kernel_launch(void* const* d_in, const int* in_sizes, int n_in,
                              void* d_out, int out_size) {
    const float* x        = (const float*)d_in[0];
    const int*   ei       = (const int*)d_in[1];
    const float* eattr    = (const float*)d_in[2];
    const float* W_l      = (const float*)d_in[3];
    const float* b_l      = (const float*)d_in[4];
    const float* W_r      = (const float*)d_in[5];
    const float* b_r      = (const float*)d_in[6];
    const float* W_e      = (const float*)d_in[7];
    const float* att      = (const float*)d_in[8];
    const float* bias_gat = (const float*)d_in[9];
    const float* W_ih     = (const float*)d_in[10];
    const float* W_hh     = (const float*)d_in[11];
    const float* b_ih     = (const float*)d_in[12];
    const float* b_hh     = (const float*)d_in[13];
    float* out = (float*)d_out;

    static cudaStream_t s1 = nullptr;
    static cudaEvent_t eRoot = nullptr, eXlr = nullptr;
    if (s1 == nullptr) {
        cudaStreamCreateWithFlags(&s1, cudaStreamNonBlocking);
        cudaEventCreateWithFlags(&eRoot, cudaEventDisableTiming);
        cudaEventCreateWithFlags(&eXlr, cudaEventDisableTiming);
        cudaFuncSetAttribute(k_xlr, cudaFuncAttributeMaxDynamicSharedMemorySize,
                             XCH * XPAD * (int)sizeof(float));
        cudaFuncSetAttribute(k_gatgru, cudaFuncAttributeMaxDynamicSharedMemorySize,
                             (int)sizeof(GGSmem));
    }

    k_nop<<<1, 32>>>();   // keeps ncu -s5 window on k_gatgru

    cudaEventRecord(eRoot, 0);
    cudaStreamWaitEvent(s1, eRoot, 0);
    k_xlr<<<SNAP * NN / XCH, 256, XCH * XPAD * sizeof(float), s1>>>(x, W_l, b_l, W_r, b_r);
    cudaEventRecord(eXlr, s1);

    k_build<<<(EE + 255) / 256, 256>>>(ei, eattr);

    cudaStreamWaitEvent(0, eXlr, 0);
    k_gatgru<<<NN / 16, 256, sizeof(GGSmem)>>>(W_e, att, bias_gat, W_ih, W_hh, b_ih, b_hh, out);
}

// round 16
// speedup vs baseline: 1.3553x; 1.0375x over previous
#include <cuda_runtime.h>
#include <math_constants.h>

#define NN    10000
#define EE    160000
#define SNAP  16       // B*T
#define TT    8
#define BB    2
#define CIN   64
#define CC    32
#define SLOTS 96       // padded bucket capacity per node (max degree ~40)
#define XCH   256      // rows per xlr block
#define XPAD  66       // smem row stride (floats): 2-way max bank conflicts

typedef unsigned long long u64;
#define F2FMA(r, x, y, z) asm("fma.rn.f32x2 %0,%1,%2,%3;" : "=l"(r) : "l"(x), "l"(y), "l"(z))
#define F2PK(r, lo, hi)   asm("mov.b64 %0,{%1,%2};"       : "=l"(r) : "f"(lo), "f"(hi))
#define F2UNPK(lo, hi, x) asm("mov.b64 {%0,%1},%2;"       : "=f"(lo), "=f"(hi) : "l"(x))

// ---------------- static device scratch (zero-initialized at load) ----------------
__device__ float g_xl[NN * SNAP * CC];       // [n][s][c]
__device__ float g_xr[NN * SNAP * CC];       // [n][s][c]
__device__ float g_loop_sum[NN * 3];
__device__ int   g_cursor[NN];               // per-node in-degree / bucket cursor
__device__ int4  g_bkt[NN * SLOTS];          // {src, attr0, attr1, attr2}

__global__ void k_nop() {}                   // ncu launch-index alignment

// ---------------- build: bucket scatter + loop_sum in ONE kernel ----------------
__global__ void k_build(const int* __restrict__ ei, const float* __restrict__ ea) {
    int e = blockIdx.x * blockDim.x + threadIdx.x;
    if (e >= EE) return;
    int src = ei[e];
    int dst = ei[EE + e];
    float a0 = ea[e * 3 + 0], a1 = ea[e * 3 + 1], a2 = ea[e * 3 + 2];
    atomicAdd(&g_loop_sum[dst * 3 + 0], a0);
    atomicAdd(&g_loop_sum[dst * 3 + 1], a1);
    atomicAdd(&g_loop_sum[dst * 3 + 2], a2);
    int pos = atomicAdd(&g_cursor[dst], 1);
    g_bkt[dst * SLOTS + pos] =
        make_int4(src, __float_as_int(a0), __float_as_int(a1), __float_as_int(a2));
}

// ---------------- xlr v3: lane = row, zero shuffles ----------------
__global__ void __launch_bounds__(256) k_xlr(const float* __restrict__ x,
                      const float* __restrict__ W_l, const float* __restrict__ b_l,
                      const float* __restrict__ W_r, const float* __restrict__ b_r) {
    extern __shared__ float sx[];            // [XCH][XPAD]
    __shared__ float4 sW[CIN][16];
    __shared__ float2 sB[CC];

    int tid = threadIdx.x;
    for (int i = tid; i < CIN * 16; i += 256) {
        int k = i >> 4, cp = i & 15;
        sW[k][cp] = make_float4(W_l[k * 32 + 2 * cp],     W_r[k * 32 + 2 * cp],
                                W_l[k * 32 + 2 * cp + 1], W_r[k * 32 + 2 * cp + 1]);
    }
    if (tid < CC) sB[tid] = make_float2(b_l[tid], b_r[tid]);

    int rbase = blockIdx.x * XCH;            // grid 625 exact
    {
        const float2* xg = (const float2*)(x + (long)rbase * CIN);
        for (int i = tid; i < XCH * 32; i += 256) {
            int row = i >> 5, q = i & 31;
            *(float2*)&sx[row * XPAD + q * 2] = xg[row * 32 + q];
        }
    }
    __syncthreads();

    int w = tid >> 5, lane = tid & 31;
    int rloc = w * 32 + lane;
    int rglob = rbase + rloc;

    float accl[32], accr[32];
#pragma unroll
    for (int c = 0; c < 32; c++) {
        float2 b = sB[c];
        accl[c] = b.x;
        accr[c] = b.y;
    }

    const float* xrow = &sx[rloc * XPAD];
#pragma unroll 4
    for (int k = 0; k < CIN; k++) {
        float xk = xrow[k];
#pragma unroll
        for (int cp = 0; cp < 16; cp++) {
            float4 wv = sW[k][cp];
            accl[2 * cp]     += xk * wv.x;
            accr[2 * cp]     += xk * wv.y;
            accl[2 * cp + 1] += xk * wv.z;
            accr[2 * cp + 1] += xk * wv.w;
        }
    }

    int s = rglob / NN, n = rglob - s * NN;
    float4* outl = (float4*)(g_xl + (n * SNAP + s) * 32);
    float4* outr = (float4*)(g_xr + (n * SNAP + s) * 32);
#pragma unroll
    for (int c4 = 0; c4 < 8; c4++) {
        outl[c4] = make_float4(accl[4 * c4], accl[4 * c4 + 1],
                               accl[4 * c4 + 2], accl[4 * c4 + 3]);
        outr[c4] = make_float4(accr[4 * c4], accr[4 * c4 + 1],
                               accr[4 * c4 + 2], accr[4 * c4 + 3]);
    }
}

// Dynamic-smem layout for k_gatgru
struct GGSmem {
    float4 sWA[32][32];     // [h][c] = {wi_r, wh_r, wi_z, wh_z}   16KB
    float2 sWB[32][32];     // [h][c] = {wi_n, wh_n}                8KB
    float2 s_tr[16][8][32]; // [nodeLocal][t][c] = {b0, b1}        32KB
    float2 s_h[8][2][32];   // [warp][nodeSel][c]                   2KB
    float  sb[6][32];
    float4 swe[3][8];
    float4 sat[8];
};

// Fused GATv2 + GRU. Block = 16 nodes, 8 warps.
// GAT: each warp processes 2 nodes sequentially.
// GRU: each warp runs 4 sequences (2 nodes x 2 batches); batch pair is a
// native f32x2 operand (s_tr/s_h float2), gates accumulated with packed FMA.
__global__ void __launch_bounds__(256, 2) k_gatgru(
        const float* __restrict__ W_e,
        const float* __restrict__ att, const float* __restrict__ bias_gat,
        const float* __restrict__ W_ih, const float* __restrict__ W_hh,
        const float* __restrict__ b_ih, const float* __restrict__ b_hh,
        float* __restrict__ out) {
    extern __shared__ char ggsm_raw[];
    GGSmem& S = *reinterpret_cast<GGSmem*>(ggsm_raw);

    int tid = threadIdx.x;
    for (int i = tid; i < 1024; i += 256) {
        int c = i & 31, hh = i >> 5;
        S.sWA[hh][c] = make_float4(W_ih[c * 32 + hh],        W_hh[c * 32 + hh],
                                   W_ih[(32 + c) * 32 + hh], W_hh[(32 + c) * 32 + hh]);
        S.sWB[hh][c] = make_float2(W_ih[(64 + c) * 32 + hh], W_hh[(64 + c) * 32 + hh]);
    }
    if (tid < 96) {
        int g = tid >> 5, c = tid & 31;
        S.sb[g][c] = b_ih[tid];
        S.sb[3 + g][c] = b_hh[tid];
    }
    if (tid < 24) S.swe[tid >> 3][tid & 7] = ((const float4*)W_e)[(tid >> 3) * 8 + (tid & 7)];
    if (tid < 8) S.sat[tid] = ((const float4*)att)[tid];
    __syncthreads();

    int w = tid >> 5, lane = tid & 31;
    int nbase = blockIdx.x * 16 + w * 2;   // grid = NN/16 exact
    int q = lane & 7, g = lane >> 3;

#define GAT_EDGE(A, EB, VALID)                                              \
    do {                                                                    \
        float a0 = __int_as_float(EB.y);                                    \
        float a1 = __int_as_float(EB.z);                                    \
        float a2 = __int_as_float(EB.w);                                    \
        float4 w0 = S.swe[0][q], w1 = S.swe[1][q], w2 = S.swe[2][q];        \
        float4 at4 = S.sat[q];                                              \
        float4 ev;                                                          \
        ev.x = a0 * w0.x + a1 * w1.x + a2 * w2.x;                           \
        ev.y = a0 * w0.y + a1 * w1.y + a2 * w2.y;                           \
        ev.z = a0 * w0.z + a1 * w1.z + a2 * w2.z;                           \
        ev.w = a0 * w0.w + a1 * w1.w + a2 * w2.w;                           \
        float d[4];                                                         \
        _Pragma("unroll")                                                   \
        for (int k = 0; k < 4; k++) {                                       \
            float v0 = A[k].x + ev.x + xr4[k].x;                            \
            float v1 = A[k].y + ev.y + xr4[k].y;                            \
            float v2 = A[k].z + ev.z + xr4[k].z;                            \
            float v3 = A[k].w + ev.w + xr4[k].w;                            \
            v0 = fmaxf(v0, 0.2f * v0);                                      \
            v1 = fmaxf(v1, 0.2f * v1);                                      \
            v2 = fmaxf(v2, 0.2f * v2);                                      \
            v3 = fmaxf(v3, 0.2f * v3);                                      \
            d[k] = v0 * at4.x + v1 * at4.y + v2 * at4.z + v3 * at4.w;       \
        }                                                                   \
        _Pragma("unroll")                                                   \
        for (int o = 1; o < 8; o <<= 1) {                                   \
            _Pragma("unroll")                                               \
            for (int k = 0; k < 4; k++)                                     \
                d[k] += __shfl_xor_sync(0xffffffffu, d[k], o);              \
        }                                                                   \
        _Pragma("unroll")                                                   \
        for (int k = 0; k < 4; k++) {                                       \
            float wv = (VALID) ? __expf(d[k]) : 0.f;                        \
            ssum[k] += wv;                                                  \
            acc[k].x += wv * A[k].x;                                        \
            acc[k].y += wv * A[k].y;                                        \
            acc[k].z += wv * A[k].z;                                        \
            acc[k].w += wv * A[k].w;                                        \
        }                                                                   \
    } while (0)

    for (int i = 0; i < 2; i++) {
        int n = nbase + i;
        int deg = g_cursor[n];

        float4 xr4[4];
        {
            const float4* p = (const float4*)(g_xr + n * SNAP * 32);
#pragma unroll
            for (int k = 0; k < 4; k++) xr4[k] = p[k * 32 + lane];
        }
        float4 acc[4];
#pragma unroll
        for (int k = 0; k < 4; k++) acc[k] = make_float4(0.f, 0.f, 0.f, 0.f);
        float ssum[4] = {0.f, 0.f, 0.f, 0.f};

        const int4* bkt = g_bkt + n * SLOTS;

        if (deg > 0) {
            int4 eb0 = bkt[0];
            float4 a[4];
            {
                const float4* xp = (const float4*)(g_xl + eb0.x * SNAP * 32);
#pragma unroll
                for (int k = 0; k < 4; k++) a[k] = xp[k * 32 + lane];
            }
            for (int j = 0; j < deg; j += 2) {
                int j1 = (j + 1 < deg) ? j + 1 : j;
                int4 eb1 = bkt[j1];
                const float4* xp1 = (const float4*)(g_xl + eb1.x * SNAP * 32);
                float4 an[4];
#pragma unroll
                for (int k = 0; k < 4; k++) an[k] = xp1[k * 32 + lane];

                GAT_EDGE(a, eb0, true);

                int j2 = (j + 2 < deg) ? j + 2 : deg - 1;
                eb0 = bkt[j2];
                const float4* xp2 = (const float4*)(g_xl + eb0.x * SNAP * 32);
#pragma unroll
                for (int k = 0; k < 4; k++) a[k] = xp2[k * 32 + lane];

                GAT_EDGE(an, eb1, (j + 1 < deg));
            }
        }

        // self-loop tail (attrs = segment mean; src = n)
        {
            float invc = 1.f / fmaxf((float)deg, 1.f);
            int4 ebs = make_int4(n,
                __float_as_int(g_loop_sum[n * 3 + 0] * invc),
                __float_as_int(g_loop_sum[n * 3 + 1] * invc),
                __float_as_int(g_loop_sum[n * 3 + 2] * invc));
            const float4* xps = (const float4*)(g_xl + n * SNAP * 32);
            float4 as[4];
#pragma unroll
            for (int k = 0; k < 4; k++) as[k] = xps[k * 32 + lane];
            GAT_EDGE(as, ebs, true);
        }

        // write normalized + biased result into transpose buffer
        {
            const float4 bi4 = *(const float4*)(bias_gat + 4 * q);
            int nl = w * 2 + i;
#pragma unroll
            for (int k = 0; k < 4; k++) {
                float inv = 1.f / ssum[k];
                int s = 4 * k + g;
                int b = s >> 3, t = s & 7;
                float* tp = (float*)&S.s_tr[nl][t][4 * q];
                tp[0 * 2 + b] = acc[k].x * inv + bi4.x;
                tp[1 * 2 + b] = acc[k].y * inv + bi4.y;
                tp[2 * 2 + b] = acc[k].z * inv + bi4.z;
                tp[3 * 2 + b] = acc[k].w * inv + bi4.w;
            }
        }
    }
#undef GAT_EDGE
    __syncwarp();

    // ---- GRU phase: lane = channel c; 4 sequences (2 nodes x 2 batches)
    // Packed f32x2 over the batch pair; r/z gates accumulate i+h jointly.
    int c = lane;
    int nl0 = w * 2, nl1 = w * 2 + 1;
    int n0 = nbase, n1 = nbase + 1;
    u64 GR, GZ, GIN, GHN;   // per-t initial accumulator values (bias sums)
    {
        float br_ = S.sb[0][c] + S.sb[3][c];
        float bz_ = S.sb[1][c] + S.sb[4][c];
        float bn_i = S.sb[2][c];
        float bn_h = S.sb[5][c];
        F2PK(GR, br_, br_);
        F2PK(GZ, bz_, bz_);
        F2PK(GIN, bn_i, bn_i);
        F2PK(GHN, bn_h, bn_h);
    }

    float h00 = 0.f, h01 = 0.f, h10 = 0.f, h11 = 0.f;  // [node][batch]
    for (int t = 0; t < TT; t++) {
        S.s_h[w][0][c] = make_float2(h00, h01);
        S.s_h[w][1][c] = make_float2(h10, h11);
        __syncwarp();

        u64 gr0 = GR, gz0 = GZ, gin0 = GIN, ghn0 = GHN;
        u64 gr1 = GR, gz1 = GZ, gin1 = GIN, ghn1 = GHN;
#pragma unroll
        for (int hh = 0; hh < 32; hh++) {
            u64 xv0 = *(const u64*)&S.s_tr[nl0][t][hh];   // {x_b0, x_b1}
            u64 xv1 = *(const u64*)&S.s_tr[nl1][t][hh];
            u64 hv0 = *(const u64*)&S.s_h[w][0][hh];      // {h_b0, h_b1}
            u64 hv1 = *(const u64*)&S.s_h[w][1][hh];
            float4 wA = S.sWA[hh][c];
            float2 wB = S.sWB[hh][c];
            u64 wir, whr, wiz, whz, win, whn;
            F2PK(wir, wA.x, wA.x);
            F2PK(whr, wA.y, wA.y);
            F2PK(wiz, wA.z, wA.z);
            F2PK(whz, wA.w, wA.w);
            F2PK(win, wB.x, wB.x);
            F2PK(whn, wB.y, wB.y);
            F2FMA(gr0, xv0, wir, gr0);
            F2FMA(gr0, hv0, whr, gr0);
            F2FMA(gz0, xv0, wiz, gz0);
            F2FMA(gz0, hv0, whz, gz0);
            F2FMA(gin0, xv0, win, gin0);
            F2FMA(ghn0, hv0, whn, ghn0);
            F2FMA(gr1, xv1, wir, gr1);
            F2FMA(gr1, hv1, whr, gr1);
            F2FMA(gz1, xv1, wiz, gz1);
            F2FMA(gz1, hv1, whz, gz1);
            F2FMA(gin1, xv1, win, gin1);
            F2FMA(ghn1, hv1, whn, ghn1);
        }
#define GRU_OUT2(GRp, GZp, GINp, GHNp, H0, H1, N)                           \
        do {                                                                \
            float r0_, r1_, z0_, z1_, i0_, i1_, hn0_, hn1_;                 \
            F2UNPK(r0_, r1_, GRp);                                          \
            F2UNPK(z0_, z1_, GZp);                                          \
            F2UNPK(i0_, i1_, GINp);                                         \
            F2UNPK(hn0_, hn1_, GHNp);                                       \
            {                                                               \
                float r = 1.f / (1.f + __expf(-r0_));                       \
                float z = 1.f / (1.f + __expf(-z0_));                       \
                float pre = i0_ + r * hn0_;                                 \
                float e2 = __expf(-2.f * pre);                              \
                float nn_ = 2.f / (1.f + e2) - 1.f;                         \
                H0 = (1.f - z) * nn_ + z * H0;                              \
                out[((long)(0 * TT + t) * NN + (N)) * 32 + c] = H0;         \
            }                                                               \
            {                                                               \
                float r = 1.f / (1.f + __expf(-r1_));                       \
                float z = 1.f / (1.f + __expf(-z1_));                       \
                float pre = i1_ + r * hn1_;                                 \
                float e2 = __expf(-2.f * pre);                              \
                float nn_ = 2.f / (1.f + e2) - 1.f;                         \
                H1 = (1.f - z) * nn_ + z * H1;                              \
                out[((long)(1 * TT + t) * NN + (N)) * 32 + c] = H1;         \
            }                                                               \
        } while (0)
        GRU_OUT2(gr0, gz0, gin0, ghn0, h00, h01, n0);
        GRU_OUT2(gr1, gz1, gin1, ghn1, h10, h11, n1);
#undef GRU_OUT2
        __syncwarp();   // protect s_h WAR before next iteration's store
    }

    // epilogue: re-zero per-node counters for the NEXT replay (warp owns n0,n1)
    if (lane < 3) g_loop_sum[n0 * 3 + lane] = 0.f;
    else if (lane == 3) g_cursor[n0] = 0;
    else if (lane >= 4 && lane < 7) g_loop_sum[n1 * 3 + (lane - 4)] = 0.f;
    else if (lane == 7) g_cursor[n1] = 0;
}

// ---------------- launch: dummy + 3 kernels, xlr forked ----------------
extern "C" void kernel_launch(void* const* d_in, const int* in_sizes, int n_in,
                              void* d_out, int out_size) {
    const float* x        = (const float*)d_in[0];
    const int*   ei       = (const int*)d_in[1];
    const float* eattr    = (const float*)d_in[2];
    const float* W_l      = (const float*)d_in[3];
    const float* b_l      = (const float*)d_in[4];
    const float* W_r      = (const float*)d_in[5];
    const float* b_r      = (const float*)d_in[6];
    const float* W_e      = (const float*)d_in[7];
    const float* att      = (const float*)d_in[8];
    const float* bias_gat = (const float*)d_in[9];
    const float* W_ih     = (const float*)d_in[10];
    const float* W_hh     = (const float*)d_in[11];
    const float* b_ih     = (const float*)d_in[12];
    const float* b_hh     = (const float*)d_in[13];
    float* out = (float*)d_out;

    static cudaStream_t s1 = nullptr;
    static cudaEvent_t eRoot = nullptr, eXlr = nullptr;
    if (s1 == nullptr) {
        cudaStreamCreateWithFlags(&s1, cudaStreamNonBlocking);
        cudaEventCreateWithFlags(&eRoot, cudaEventDisableTiming);
        cudaEventCreateWithFlags(&eXlr, cudaEventDisableTiming);
        cudaFuncSetAttribute(k_xlr, cudaFuncAttributeMaxDynamicSharedMemorySize,
                             XCH * XPAD * (int)sizeof(float));
        cudaFuncSetAttribute(k_gatgru, cudaFuncAttributeMaxDynamicSharedMemorySize,
                             (int)sizeof(GGSmem));
    }

    k_nop<<<1, 32>>>();   // keeps ncu -s5 window on k_gatgru

    cudaEventRecord(eRoot, 0);
    cudaStreamWaitEvent(s1, eRoot, 0);
    k_xlr<<<SNAP * NN / XCH, 256, XCH * XPAD * sizeof(float), s1>>>(x, W_l, b_l, W_r, b_r);
    cudaEventRecord(eXlr, s1);

    k_build<<<(EE + 255) / 256, 256>>>(ei, eattr);

    cudaStreamWaitEvent(0, eXlr, 0);
    k_gatgru<<<NN / 16, 256, sizeof(GGSmem)>>>(W_e, att, bias_gat, W_ih, W_hh, b_ih, b_hh, out);
}